// round 1
// baseline (speedup 1.0000x reference)
#include <cuda_runtime.h>

#define BB    2048
#define TT    2049
#define SS    2048      // TT-1 (and == num_steps in the reference)
#define KK    8
#define NSEG  32
#define SEGLEN 64       // SS / NSEG
#define PADSEG 520      // 64*8 + 8 pad -> per-segment bank shift of 8 (conflict-free)
#define GAMMA_F 0.99f

// smem layout (floats):
//   sa   [NSEG*PADSEG]   per-step a
//   sm_  [NSEG*PADSEG]   per-step m
//   sA   [NSEG*KK]       segment transform A
//   sM   [NSEG*KK]       segment transform M
//   sC   [NSEG*KK]       carry-in per segment
//   red  [32]            block reduction
#define SMEM_FLOATS (2*NSEG*PADSEG + 3*NSEG*KK + 32)

__global__ __launch_bounds__(256, 1)
void retrace_loss_kernel(const float* __restrict__ q,    // state_trajectory_action_values
                         const float* __restrict__ tq,   // target_state_trajectory_action_values
                         const float* __restrict__ tv,   // target_expected_state_values
                         const float* __restrict__ rw,   // rewards
                         const float* __restrict__ olp,  // original_log_trajectory_action_probs (B,T)
                         const float* __restrict__ tlp,  // target_log_trajectory_task_action_probs (B,T,K)
                         float* __restrict__ out)
{
    extern __shared__ float smem[];
    float* sa  = smem;
    float* sm_ = sa  + NSEG * PADSEG;
    float* sA  = sm_ + NSEG * PADSEG;
    float* sM  = sA  + NSEG * KK;
    float* sC  = sM  + NSEG * KK;
    float* red = sC  + NSEG * KK;

    const int b   = blockIdx.x;
    const int tid = threadIdx.x;
    const int seg = tid >> 3;   // 0..31
    const int k   = tid & 7;    // 0..7

    const size_t base3 = (size_t)b * TT * KK;
    const size_t base2 = (size_t)b * TT;
    const int t0 = seg * SEGLEN;

    // ---------------- Phase 1: per-segment backward scan, cache (a,m), compose (A,M) ----
    float A = 0.0f, M = 1.0f;
    #pragma unroll 4
    for (int j = SEGLEN - 1; j >= 0; --j) {
        const int t = t0 + j;
        const size_t o1 = base3 + (size_t)(t + 1) * KK + k;  // [:, 1:, :] slice
        const size_t o0 = base3 + (size_t)t * KK + k;        // [:, :-1, :] slice

        const float r   = rw[o0];
        const float V   = tv[o1];
        const float Qt  = tq[o1];
        const float dl  = tlp[o1] - olp[base2 + t + 1];
        const float c   = __expf(fminf(dl, 0.0f));

        float a, m;
        if (t == SS - 1) {
            // init = r + gamma*(V + c*Qt), carry beyond is irrelevant
            a = r + GAMMA_F * fmaf(c, Qt, V);
            m = 0.0f;
        } else {
            // ret = r + gamma*(V + c*(carry - Qt)) = [r + gamma*(V - c*Qt)] + (gamma*c)*carry
            a = r + GAMMA_F * fmaf(-c, Qt, V);
            m = GAMMA_F * c;
        }
        const int sidx = seg * PADSEG + j * KK + k;
        sa[sidx]  = a;
        sm_[sidx] = m;
        A = fmaf(m, A, a);
        M = m * M;
    }
    sA[seg * KK + k] = A;
    sM[seg * KK + k] = M;
    __syncthreads();

    // ---------------- Combine: carry-in per segment (serial over 32 segments, 1 thread/k) --
    if (tid < KK) {
        float carry = 0.0f;                 // segment NSEG-1 has M=0 path (init), carry unused
        sC[(NSEG - 1) * KK + tid] = 0.0f;
        for (int s = NSEG - 2; s >= 0; --s) {
            carry = fmaf(sM[(s + 1) * KK + tid], carry, sA[(s + 1) * KK + tid]);
            sC[s * KK + tid] = carry;       // ret at t = (s+1)*SEGLEN
        }
    }
    __syncthreads();

    // ---------------- Phase 2: replay from SMEM with true carry, fuse Huber loss ---------
    float carry = sC[seg * KK + k];
    float lsum  = 0.0f;
    #pragma unroll 4
    for (int j = SEGLEN - 1; j >= 0; --j) {
        const int t = t0 + j;
        const int sidx = seg * PADSEG + j * KK + k;
        const float a = sa[sidx];
        const float m = sm_[sidx];
        const float ret = fmaf(m, carry, a);
        carry = ret;
        const float d  = q[base3 + (size_t)t * KK + k] - ret;
        const float ad = fabsf(d);
        lsum += (ad < 1.0f) ? 0.5f * d * d : (ad - 0.5f);
    }

    // ---------------- Block reduce + scaled atomic -----------------------------------
    #pragma unroll
    for (int off = 16; off > 0; off >>= 1)
        lsum += __shfl_down_sync(0xFFFFFFFFu, lsum, off);
    if ((tid & 31) == 0) red[tid >> 5] = lsum;
    __syncthreads();
    if (tid < 32) {
        float v = (tid < 8) ? red[tid] : 0.0f;
        #pragma unroll
        for (int off = 4; off > 0; off >>= 1)
            v += __shfl_down_sync(0xFFFFFFFFu, v, off);
        if (tid == 0) {
            // mean over B*SS*KK = 33554432 elements (scale is exact power of two)
            atomicAdd(out, v * (1.0f / 33554432.0f));
        }
    }
}

extern "C" void kernel_launch(void* const* d_in, const int* in_sizes, int n_in,
                              void* d_out, int out_size)
{
    (void)in_sizes; (void)n_in; (void)out_size;
    const float* q   = (const float*)d_in[0];
    const float* tq  = (const float*)d_in[1];
    const float* tv  = (const float*)d_in[2];
    const float* rw  = (const float*)d_in[3];
    const float* olp = (const float*)d_in[4];
    const float* tlp = (const float*)d_in[5];
    float* out = (float*)d_out;

    const size_t smem_bytes = SMEM_FLOATS * sizeof(float);
    cudaFuncSetAttribute(retrace_loss_kernel,
                         cudaFuncAttributeMaxDynamicSharedMemorySize,
                         (int)smem_bytes);

    cudaMemsetAsync(out, 0, sizeof(float));
    retrace_loss_kernel<<<BB, 256, smem_bytes>>>(q, tq, tv, rw, olp, tlp, out);
}

// round 3
// speedup vs baseline: 1.3848x; 1.3848x over previous
#include <cuda_runtime.h>
#include <cuda_fp16.h>
#include <cstdint>

#define BB     2048
#define TT     2049
#define SS     2048     // T-1
#define KK     8
#define HALF_T 1024     // timesteps per CTA (cluster of 2 per batch row)
#define NSEG   32
#define SEGLEN 32       // HALF_T / NSEG
#define PADF   264      // 32*8 + 8   (floats/seg; 264 mod 32 = 8 -> conflict-free shift)
#define PADH   272      // 32*8 + 16  (halves/seg; 272h = 136 words, 136 mod 32 = 8)
#define GAMMA_F 0.99f

// dynamic smem layout (bytes):
//   s_   : NSEG*PADF floats          = 33792
//   mh   : NSEG*PADH halves          = 17408
//   sA   : NSEG*KK floats            = 1024
//   sM   : NSEG*KK floats            = 1024
//   sC   : NSEG*KK floats            = 1024
//   sXin : KK floats                 = 32
//   red  : 32 floats                 = 128
#define SMEM_BYTES (NSEG*PADF*4 + NSEG*PADH*2 + 3*NSEG*KK*4 + KK*4 + 32*4)

__device__ __forceinline__ uint32_t smem_u32(const void* p) {
    uint32_t a;
    asm("{ .reg .u64 t; cvta.to.shared.u64 t, %1; cvt.u32.u64 %0, t; }"
        : "=r"(a) : "l"(p));
    return a;
}

__global__ __launch_bounds__(256, 4) __cluster_dims__(2, 1, 1)
void retrace_loss_kernel(const float* __restrict__ q,
                         const float* __restrict__ tq,
                         const float* __restrict__ tv,
                         const float* __restrict__ rw,
                         const float* __restrict__ olp,
                         const float* __restrict__ tlp,
                         float* __restrict__ out)
{
    extern __shared__ char smem[];
    float*  s_  = (float*)smem;
    __half* mh  = (__half*)(s_ + NSEG * PADF);
    float*  sA  = (float*)((char*)smem + NSEG*PADF*4 + NSEG*PADH*2);
    float*  sM  = sA + NSEG * KK;
    float*  sC  = sM + NSEG * KK;
    float*  sXin = sC + NSEG * KK;
    float*  red  = sXin + KK;

    const int tid = threadIdx.x;
    const int seg = tid >> 3;   // 0..31
    const int k   = tid & 7;    // 0..7

    uint32_t half;
    asm("mov.u32 %0, %%cluster_ctarank;" : "=r"(half));
    const int b = blockIdx.x >> 1;

    const size_t base3 = (size_t)b * TT * KK;
    const size_t base2 = (size_t)b * TT;
    const int tbase = (int)half * HALF_T + seg * SEGLEN;

    // ---- Phase 1: backward scan; build suffix (Asuf, Msuf); cache s=q-Asuf, Msuf ----
    float A = 0.0f, M = 1.0f;
    #pragma unroll 4
    for (int j = SEGLEN - 1; j >= 0; --j) {
        const int t = tbase + j;
        const size_t o1 = base3 + (size_t)(t + 1) * KK + k;
        const size_t o0 = base3 + (size_t)t * KK + k;

        const float r   = rw[o0];
        const float V   = tv[o1];
        const float Qt  = tq[o1];
        const float tl  = tlp[o1];
        const float ol  = olp[base2 + t + 1];
        const float qq  = q[o0];

        const float c = __expf(fminf(tl - ol, 0.0f));
        const bool last = (t == SS - 1);
        const float cq = last ? c : -c;                 // init: +c*Qt ; else -c*Qt
        const float a  = fmaf(GAMMA_F, fmaf(cq, Qt, V), r);
        const float m  = last ? 0.0f : GAMMA_F * c;

        A = fmaf(m, A, a);      // Asuf over [j .. seg end]
        M = m * M;              // Msuf over [j .. seg end]

        s_[seg * PADF + j * KK + k] = qq - A;
        mh[seg * PADH + j * KK + k] = __float2half_rn(M);
    }
    sA[seg * KK + k] = A;
    sM[seg * KK + k] = M;
    __syncthreads();

    // ---- CTA1 (upper half, contains init): local segment carries + export ret(t=1024) ----
    if (half == 1 && tid < KK) {
        float carry = 0.0f;
        sC[(NSEG - 1) * KK + tid] = 0.0f;   // seg 31 contains init; carry unused (M=0)
        #pragma unroll 1
        for (int s = NSEG - 2; s >= 0; --s) {
            carry = fmaf(sM[(s + 1) * KK + tid], carry, sA[(s + 1) * KK + tid]);
            sC[s * KK + tid] = carry;
        }
        const float x1024 = fmaf(sM[tid], carry, sA[tid]);  // ret at t = 1024
        // DSMEM store into rank-0 CTA's sXin[tid]
        uint32_t laddr = smem_u32(&sXin[tid]);
        uint32_t raddr;
        asm("mapa.shared::cluster.u32 %0, %1, %2;" : "=r"(raddr) : "r"(laddr), "r"(0));
        asm volatile("st.shared::cluster.f32 [%0], %1;" :: "r"(raddr), "f"(x1024) : "memory");
    }

    // cluster barrier: release CTA1's DSMEM store, acquire before CTA0 reads sXin
    asm volatile("barrier.cluster.arrive.aligned;" ::: "memory");
    asm volatile("barrier.cluster.wait.aligned;"   ::: "memory");

    // ---- CTA0 (lower half): segment carries seeded with ret(t=1024) ----
    if (half == 0 && tid < KK) {
        float carry = sXin[tid];
        sC[(NSEG - 1) * KK + tid] = carry;
        #pragma unroll 1
        for (int s = NSEG - 2; s >= 0; --s) {
            carry = fmaf(sM[(s + 1) * KK + tid], carry, sA[(s + 1) * KK + tid]);
            sC[s * KK + tid] = carry;
        }
    }
    __syncthreads();

    // ---- Phase 2: element-parallel loss from smem: d = s - Msuf*carry ----
    const float carry = sC[seg * KK + k];
    float lsum = 0.0f;
    #pragma unroll 8
    for (int j = 0; j < SEGLEN; ++j) {
        const float sv = s_[seg * PADF + j * KK + k];
        const float mv = __half2float(mh[seg * PADH + j * KK + k]);
        const float d  = fmaf(-mv, carry, sv);
        const float ad = fabsf(d);
        lsum += (ad < 1.0f) ? 0.5f * d * d : (ad - 0.5f);
    }

    // ---- block reduce + scaled atomic ----
    #pragma unroll
    for (int off = 16; off > 0; off >>= 1)
        lsum += __shfl_down_sync(0xFFFFFFFFu, lsum, off);
    if ((tid & 31) == 0) red[tid >> 5] = lsum;
    __syncthreads();
    if (tid < 32) {
        float v = (tid < 8) ? red[tid] : 0.0f;
        #pragma unroll
        for (int off = 4; off > 0; off >>= 1)
            v += __shfl_down_sync(0xFFFFFFFFu, v, off);
        if (tid == 0)
            atomicAdd(out, v * (1.0f / 33554432.0f));   // mean over 2048*2048*8
    }
}

extern "C" void kernel_launch(void* const* d_in, const int* in_sizes, int n_in,
                              void* d_out, int out_size)
{
    (void)in_sizes; (void)n_in; (void)out_size;
    const float* q   = (const float*)d_in[0];
    const float* tq  = (const float*)d_in[1];
    const float* tv  = (const float*)d_in[2];
    const float* rw  = (const float*)d_in[3];
    const float* olp = (const float*)d_in[4];
    const float* tlp = (const float*)d_in[5];
    float* out = (float*)d_out;

    cudaFuncSetAttribute(retrace_loss_kernel,
                         cudaFuncAttributeMaxDynamicSharedMemorySize,
                         SMEM_BYTES);

    cudaMemsetAsync(out, 0, sizeof(float));
    retrace_loss_kernel<<<BB * 2, 256, SMEM_BYTES>>>(q, tq, tv, rw, olp, tlp, out);
}